// round 2
// baseline (speedup 1.0000x reference)
#include <cuda_runtime.h>
#include <cstdint>
#include <cfloat>
#include <math.h>

#define BQ   32
#define SEQ  128
#define DIM  512
#define NMEM 131072
#define RNK  16
#define TOPK 8

#define OUT_RET 0
#define OUT_HID (BQ*TOPK*DIM)          /* 131072 */
#define OUT_MEM (OUT_HID + BQ*DIM)     /* 147456 */

// ---------------- scratch (static device globals; no allocations) ----------------
__device__ float g_q[BQ*DIM];
__device__ float g_qB[BQ*RNK];
__device__ float g_scores[(size_t)BQ*NMEM];
__device__ int   g_topidx[BQ*TOPK];
__device__ float g_xT[DIM*BQ];          // transposed x for coalesced GEMV reads
__device__ float g_gx[BQ*3*DIM];
__device__ float g_p[BQ];

// packed fp32x2 FMA (Blackwell; bit-exact fp32, 2x FFMA throughput)
__device__ __forceinline__ void fma2(unsigned long long& d,
                                     unsigned long long a, unsigned long long b) {
    asm("fma.rn.f32x2 %0, %1, %2, %0;" : "+l"(d) : "l"(a), "l"(b));
}

__device__ __forceinline__ float sigmoidf_(float x) { return 1.f/(1.f + expf(-x)); }

// tie-break compare matching lax.top_k (desc value, asc index on ties)
__device__ __forceinline__ bool gtp(float v1, int i1, float v2, int i2) {
    return (v1 > v2) || (v1 == v2 && i1 < i2);
}

// ---------------- Kernel A: q = mean_s(query); qB = q @ loraB^T ----------------
__global__ void kA(const float* __restrict__ query, const float* __restrict__ loraB) {
    int b = blockIdx.x, t = threadIdx.x;
    __shared__ float sq[DIM];
    for (int d = t; d < DIM; d += 256) {
        const float* p = query + ((size_t)b*SEQ)*DIM + d;
        float acc = 0.f;
        #pragma unroll 8
        for (int s = 0; s < SEQ; s++) acc += p[(size_t)s*DIM];
        float qv = acc * (1.0f/SEQ);
        sq[d] = qv;
        g_q[b*DIM + d] = qv;
    }
    __syncthreads();
    int w = t >> 5, lane = t & 31;
    for (int r = w; r < RNK; r += 8) {
        float acc = 0.f;
        for (int d = lane; d < DIM; d += 32) acc += sq[d] * loraB[r*DIM + d];
        #pragma unroll
        for (int o = 16; o; o >>= 1) acc += __shfl_xor_sync(0xffffffffu, acc, o);
        if (lane == 0) g_qB[b*RNK + r] = acc;
    }
}

// ---------------- Kernel B: scores for all N + stream-copy base -> new_mem -------
#define TN 128
#define DC 32
#define WPAD (DC + 2)   // 34 words: row-group LDS.64 pattern hits all 32 banks once

__global__ __launch_bounds__(128) void kB(const float* __restrict__ base,
                                          const float* __restrict__ loraA,
                                          float* __restrict__ out) {
    __shared__ float sB[TN][WPAD];
    __shared__ float sQ[BQ][DC];
    __shared__ float sQB[BQ][RNK];
    int t  = threadIdx.x;
    int n0 = blockIdx.x * TN;
    int bg = t >> 4;   // 0..7  (4 batches each)
    int rg = t & 15;   // 0..15 (8 rows each, stride 16)

    for (int i = t; i < BQ*RNK; i += 128) ((float*)sQB)[i] = g_qB[i];

    unsigned long long acc[4][8];
    #pragma unroll
    for (int i = 0; i < 4; i++)
        #pragma unroll
        for (int j = 0; j < 8; j++) acc[i][j] = 0ull;

    float* omem = out + OUT_MEM;

    for (int c = 0; c < DIM/DC; c++) {
        int d0 = c*DC;
        __syncthreads();
        // load 128x32 base tile -> shared (padded), and fused copy to new_mem
        #pragma unroll
        for (int i = 0; i < 8; i++) {
            int e = t + i*128;           // 0..1023 float4s
            int row = e >> 3, qd = e & 7;
            const float4 v = *(const float4*)(base + (size_t)(n0+row)*DIM + d0 + qd*4);
            *(float2*)&sB[row][qd*4]     = make_float2(v.x, v.y);
            *(float2*)&sB[row][qd*4 + 2] = make_float2(v.z, v.w);
            *(float4*)(omem + (size_t)(n0+row)*DIM + d0 + qd*4) = v;
        }
        // load 32x32 q chunk
        #pragma unroll
        for (int i = 0; i < 2; i++) {
            int e = t + i*128;           // 0..255 float4s
            int bb = e >> 3, qd = e & 7;
            *(float4*)&sQ[bb][qd*4] = *(const float4*)(g_q + bb*DIM + d0 + qd*4);
        }
        __syncthreads();
        // 4 batches x 8 rows register tile, f32x2 packed along D
        #pragma unroll
        for (int dd = 0; dd < DC; dd += 2) {
            unsigned long long q2[4], r2[8];
            #pragma unroll
            for (int i = 0; i < 4; i++)
                q2[i] = *(const unsigned long long*)&sQ[bg*4 + i][dd];
            #pragma unroll
            for (int j = 0; j < 8; j++)
                r2[j] = *(const unsigned long long*)&sB[rg + 16*j][dd];
            #pragma unroll
            for (int i = 0; i < 4; i++)
                #pragma unroll
                for (int j = 0; j < 8; j++)
                    fma2(acc[i][j], q2[i], r2[j]);
        }
    }

    // epilogue: + qB . A[n] (rank-16 LoRA term), write scores
    #pragma unroll
    for (int j = 0; j < 8; j++) {
        int n = n0 + rg + 16*j;
        const float4* ap = (const float4*)(loraA + (size_t)n*RNK);
        float4 a0 = ap[0], a1 = ap[1], a2 = ap[2], a3 = ap[3];
        #pragma unroll
        for (int i = 0; i < 4; i++) {
            int b = bg*4 + i;
            float2 f = *(float2*)&acc[i][j];
            float s = f.x + f.y;
            const float* qb = sQB[b];
            s += qb[0]*a0.x + qb[1]*a0.y + qb[2]*a0.z + qb[3]*a0.w;
            s += qb[4]*a1.x + qb[5]*a1.y + qb[6]*a1.z + qb[7]*a1.w;
            s += qb[8]*a2.x + qb[9]*a2.y + qb[10]*a2.z + qb[11]*a2.w;
            s += qb[12]*a3.x + qb[13]*a3.y + qb[14]*a3.z + qb[15]*a3.w;
            g_scores[(size_t)b*NMEM + n] = s;
        }
    }
}

// ---------------- Kernel C: top-8 per batch (sorted desc, lax.top_k order) -------
__global__ void kC() {
    int b = blockIdx.x, t = threadIdx.x;   // 256 threads
    const float* sc = g_scores + (size_t)b*NMEM;
    float bv[TOPK]; int bi[TOPK];
    #pragma unroll
    for (int k = 0; k < TOPK; k++) { bv[k] = -FLT_MAX; bi[k] = 0x7fffffff; }

    for (int i = 0; i < NMEM/(256*4); i++) {
        int e4 = t + i*256;
        float4 v = *(const float4*)(sc + (size_t)e4*4);
        float vv[4] = {v.x, v.y, v.z, v.w};
        #pragma unroll
        for (int j = 0; j < 4; j++) {
            float cv = vv[j]; int ci = e4*4 + j;
            if (gtp(cv, ci, bv[TOPK-1], bi[TOPK-1])) {
                #pragma unroll
                for (int k = 0; k < TOPK; k++) {
                    if (gtp(cv, ci, bv[k], bi[k])) {
                        float tv = bv[k]; int ti = bi[k];
                        bv[k] = cv; bi[k] = ci;
                        cv = tv; ci = ti;
                    }
                }
            }
        }
    }

    __shared__ float sv[256*TOPK];
    __shared__ int   si[256*TOPK];
    __shared__ float rv[256];
    __shared__ int   ri[256];
    __shared__ int   rl[256];
    #pragma unroll
    for (int k = 0; k < TOPK; k++) { sv[t*TOPK+k] = bv[k]; si[t*TOPK+k] = bi[k]; }
    __syncthreads();

    for (int kk = 0; kk < TOPK; kk++) {
        float mv = -FLT_MAX; int mi = 0x7fffffff; int ml = 0;
        #pragma unroll
        for (int k = 0; k < TOPK; k++) {
            float v = sv[t*TOPK+k]; int ii = si[t*TOPK+k];
            if (gtp(v, ii, mv, mi)) { mv = v; mi = ii; ml = t*TOPK+k; }
        }
        rv[t] = mv; ri[t] = mi; rl[t] = ml;
        __syncthreads();
        for (int s2 = 128; s2 > 0; s2 >>= 1) {
            if (t < s2 && gtp(rv[t+s2], ri[t+s2], rv[t], ri[t])) {
                rv[t] = rv[t+s2]; ri[t] = ri[t+s2]; rl[t] = rl[t+s2];
            }
            __syncthreads();
        }
        if (t == 0) { g_topidx[b*TOPK + kk] = ri[0]; sv[rl[0]] = -FLT_MAX; }
        __syncthreads();
    }
}

// ---------------- Kernel D1: retrieved = base[idx] + A[idx]@loraB; x = sum_k -----
__global__ void kD1(const float* __restrict__ base, const float* __restrict__ loraA,
                    const float* __restrict__ loraB, float* __restrict__ out) {
    int b = blockIdx.x, t = threadIdx.x;   // 512 threads, t == d
    __shared__ int   sIdx[TOPK];
    __shared__ float sA[TOPK][RNK];
    if (t < TOPK) sIdx[t] = g_topidx[b*TOPK + t];
    __syncthreads();
    if (t < TOPK*RNK) sA[t/RNK][t%RNK] = loraA[(size_t)sIdx[t/RNK]*RNK + (t%RNK)];
    __syncthreads();
    float lb[RNK];
    #pragma unroll
    for (int r = 0; r < RNK; r++) lb[r] = loraB[r*DIM + t];
    float x = 0.f;
    #pragma unroll
    for (int k = 0; k < TOPK; k++) {
        float v = base[(size_t)sIdx[k]*DIM + t];
        #pragma unroll
        for (int r = 0; r < RNK; r++) v += sA[k][r]*lb[r];
        out[OUT_RET + ((size_t)(b*TOPK + k))*DIM + t] = v;
        x += v;
    }
    g_xT[t*BQ + b] = x;
}

// ---------------- Kernel D2: gx = x @ w_ih^T + b_ih ------------------------------
__global__ void kD2(const float* __restrict__ w_ih, const float* __restrict__ b_ih) {
    __shared__ float sW[8][DIM];
    int t = threadIdx.x, g0 = blockIdx.x*8;   // 256 threads, 8 gate rows/block
    for (int e = t; e < 8*DIM; e += 256)
        ((float*)sW)[e] = w_ih[(size_t)g0*DIM + e];
    __syncthreads();
    int b = t & 31, g = t >> 5;
    const float* xp = g_xT + b;
    const float* wp = sW[g];
    float acc = 0.f;
    #pragma unroll 8
    for (int d = 0; d < DIM; d++) acc += xp[d*BQ] * wp[d];
    g_gx[b*3*DIM + g0 + g] = acc + b_ih[g0 + g];
}

// ---------------- Kernel D2b: GRU gates (h0=0), hidden, write_prob --------------
__global__ void kD2b(const float* __restrict__ b_hh, const float* __restrict__ wg_w,
                     const float* __restrict__ wg_b, float* __restrict__ out) {
    int b = blockIdx.x, t = threadIdx.x;   // 512 threads, t == d
    float gxr = g_gx[b*3*DIM + t];
    float gxz = g_gx[b*3*DIM + DIM + t];
    float gxn = g_gx[b*3*DIM + 2*DIM + t];
    float r = sigmoidf_(gxr + b_hh[t]);
    float z = sigmoidf_(gxz + b_hh[DIM + t]);
    float n = tanhf(gxn + r*b_hh[2*DIM + t]);
    float h = (1.f - z)*n;                 // + z*h0, h0 = 0
    out[OUT_HID + b*DIM + t] = h;
    float pr = h * wg_w[t];
    #pragma unroll
    for (int o = 16; o; o >>= 1) pr += __shfl_xor_sync(0xffffffffu, pr, o);
    __shared__ float sp[16];
    if ((t & 31) == 0) sp[t >> 5] = pr;
    __syncthreads();
    if (t == 0) {
        float s = 0.f;
        #pragma unroll
        for (int i = 0; i < 16; i++) s += sp[i];
        g_p[b] = sigmoidf_(s + wg_b[0]);
    }
}

// ---------------- Kernel E: sequential-in-batch scatter into new_mem -------------
__global__ void kE(float* __restrict__ out) {
    float* mem = out + OUT_MEM;
    int t = threadIdx.x;   // 512 threads, t == d
    for (int b = 0; b < BQ; b++) {
        float p   = g_p[b];
        float add = p * g_q[b*DIM + t];
        float om  = 1.f - p;
        #pragma unroll
        for (int k = 0; k < TOPK; k++) {
            size_t off = (size_t)g_topidx[b*TOPK + k]*DIM + t;
            mem[off] = om*mem[off] + add;
        }
        __syncthreads();  // batch order matters if indices collide across batches
    }
}

// ---------------- launch ---------------------------------------------------------
extern "C" void kernel_launch(void* const* d_in, const int* in_sizes, int n_in,
                              void* d_out, int out_size) {
    const float* query = (const float*)d_in[0];
    const float* base  = (const float*)d_in[1];
    const float* loraA = (const float*)d_in[2];
    const float* loraB = (const float*)d_in[3];
    const float* w_ih  = (const float*)d_in[4];
    // d_in[5] = gru_w_hh: unused (h0 == 0)
    const float* b_ih  = (const float*)d_in[6];
    const float* b_hh  = (const float*)d_in[7];
    const float* wg_w  = (const float*)d_in[8];
    const float* wg_b  = (const float*)d_in[9];
    float* out = (float*)d_out;

    kA  <<<BQ, 256>>>(query, loraB);
    kB  <<<NMEM/TN, 128>>>(base, loraA, out);
    kC  <<<BQ, 256>>>();
    kD1 <<<BQ, DIM>>>(base, loraA, loraB, out);
    kD2 <<<(3*DIM)/8, 256>>>(w_ih, b_ih);
    kD2b<<<BQ, DIM>>>(b_hh, wg_w, wg_b, out);
    kE  <<<1, DIM>>>(out);
}

// round 3
// speedup vs baseline: 1.4104x; 1.4104x over previous
#include <cuda_runtime.h>
#include <cstdint>
#include <cfloat>
#include <math.h>

#define BQ   32
#define SEQ  128
#define DIM  512
#define NMEM 131072
#define RNK  16
#define TOPK 8

#define OUT_RET 0
#define OUT_HID (BQ*TOPK*DIM)          /* 131072 */
#define OUT_MEM (OUT_HID + BQ*DIM)     /* 147456 */

// ---------------- scratch (static device globals; no allocations) ----------------
__device__ float g_q[BQ*DIM];
__device__ float g_qB[BQ*RNK];
__device__ float g_scores[(size_t)BQ*NMEM];
__device__ int   g_topidx[BQ*TOPK];
__device__ float g_xT[DIM*BQ];
__device__ float g_gx[BQ*3*DIM];
__device__ float g_p[BQ];

// packed fp32x2 FMA (Blackwell; bit-exact fp32 pairs, 2x FFMA throughput)
__device__ __forceinline__ void fma2(unsigned long long& d,
                                     unsigned long long a, unsigned long long b) {
    asm("fma.rn.f32x2 %0, %1, %2, %0;" : "+l"(d) : "l"(a), "l"(b));
}

// 8-byte cp.async global->shared
__device__ __forceinline__ void cpa8(void* dst_smem, const void* src) {
    unsigned d = (unsigned)__cvta_generic_to_shared(dst_smem);
    asm volatile("cp.async.ca.shared.global [%0], [%1], 8;" :: "r"(d), "l"(src));
}
__device__ __forceinline__ void cpa_commit() {
    asm volatile("cp.async.commit_group;" ::: "memory");
}

__device__ __forceinline__ float sigmoidf_(float x) { return 1.f/(1.f + expf(-x)); }

// tie-break compare matching lax.top_k (desc value, asc index on ties)
__device__ __forceinline__ bool gtp(float v1, int i1, float v2, int i2) {
    return (v1 > v2) || (v1 == v2 && i1 < i2);
}

// ---------------- Kernel A: q = mean_s(query) -----------------------------------
__global__ void kA(const float* __restrict__ query) {
    int b = blockIdx.x, t = threadIdx.x;
    for (int d = t; d < DIM; d += 256) {
        const float* p = query + ((size_t)b*SEQ)*DIM + d;
        float acc = 0.f;
        #pragma unroll 8
        for (int s = 0; s < SEQ; s++) acc += p[(size_t)s*DIM];
        g_q[b*DIM + d] = acc * (1.0f/SEQ);
    }
}

// ---------------- Kernel X: qB = q @ loraB^T ------------------------------------
__global__ void kX(const float* __restrict__ loraB) {
    int b = blockIdx.x, t = threadIdx.x;   // 256 threads
    int w = t >> 5, lane = t & 31;
    for (int r = w; r < RNK; r += 8) {
        float acc = 0.f;
        for (int d = lane; d < DIM; d += 32) acc += g_q[b*DIM + d] * loraB[r*DIM + d];
        #pragma unroll
        for (int o = 16; o; o >>= 1) acc += __shfl_xor_sync(0xffffffffu, acc, o);
        if (lane == 0) g_qB[b*RNK + r] = acc;
    }
}

// ---------------- Kernel Y: tiny placeholder (launch-slot alignment for ncu) -----
__global__ void kY() {
    if (threadIdx.x < BQ) g_p[threadIdx.x] = 0.f;   // overwritten by kD2b before use
}

// ---------------- Kernel B: scores for all N + fused base -> new_mem copy --------
// 64 threads/block, 8 batches x 8 rows per thread (f32x2), cp.async double-buffer.
#define TN   128
#define DC   32
#define NCH  (DIM/DC)
#define WPAD 34
#define KBT  64

__global__ __launch_bounds__(KBT) void kB(const float* __restrict__ base,
                                          const float* __restrict__ loraA,
                                          float* __restrict__ out) {
    __shared__ float sB[2][TN][WPAD];   // 34816 B
    __shared__ float sQ[2][BQ][WPAD];   //  8704 B
    __shared__ float sQB[BQ][RNK];      //  2048 B
    const int t  = threadIdx.x;
    const int n0 = blockIdx.x * TN;
    const int w  = t >> 5, l = t & 31;
    const int bgq = (w << 1) | (l >> 4);   // 0..3 -> 8 batches each
    const int rg  = l & 15;                // rows rg + 16*j

    for (int i = t; i < BQ*RNK; i += KBT) ((float*)sQB)[i] = g_qB[i];

    auto fill = [&](int c, int buf) {
        int d0 = c*DC;
        #pragma unroll
        for (int i = 0; i < 32; i++) {
            int g = t + i*KBT;                 // 2048 8B-granules: 128 rows x 16
            int row = g >> 4, gw = g & 15;
            cpa8(&sB[buf][row][gw*2], base + (size_t)(n0+row)*DIM + d0 + gw*2);
        }
        #pragma unroll
        for (int i = 0; i < 8; i++) {
            int g = t + i*KBT;                 // 512 granules: 32 rows x 16
            int row = g >> 4, gw = g & 15;
            cpa8(&sQ[buf][row][gw*2], g_q + row*DIM + d0 + gw*2);
        }
    };

    unsigned long long acc[8][8];
    #pragma unroll
    for (int i = 0; i < 8; i++)
        #pragma unroll
        for (int j = 0; j < 8; j++) acc[i][j] = 0ull;

    float* omem = out + OUT_MEM;

    fill(0, 0); cpa_commit();

    for (int c = 0; c < NCH; c++) {
        const int buf = c & 1;
        if (c + 1 < NCH) { fill(c + 1, buf ^ 1); cpa_commit(); }
        if (c + 1 < NCH) asm volatile("cp.async.wait_group 1;" ::: "memory");
        else             asm volatile("cp.async.wait_group 0;" ::: "memory");
        __syncthreads();

        #pragma unroll 4
        for (int dd = 0; dd < DC; dd += 2) {
            unsigned long long q2[8], r2[8];
            #pragma unroll
            for (int i = 0; i < 8; i++)
                q2[i] = *(const unsigned long long*)&sQ[buf][bgq*8 + i][dd];
            #pragma unroll
            for (int j = 0; j < 8; j++)
                r2[j] = *(const unsigned long long*)&sB[buf][rg + 16*j][dd];
            #pragma unroll
            for (int i = 0; i < 8; i++)
                #pragma unroll
                for (int j = 0; j < 8; j++)
                    fma2(acc[i][j], q2[i], r2[j]);
        }

        // fused copy: smem tile -> new_mem (no extra global reads)
        {
            int d0 = c*DC;
            #pragma unroll
            for (int i = 0; i < 16; i++) {
                int g2 = t + i*KBT;            // 1024 16B-chunks: 128 rows x 8
                int row = g2 >> 3, p = g2 & 7;
                float2 f0 = *(const float2*)&sB[buf][row][p*4];
                float2 f1 = *(const float2*)&sB[buf][row][p*4 + 2];
                *(float4*)(omem + (size_t)(n0+row)*DIM + d0 + p*4) =
                    make_float4(f0.x, f0.y, f1.x, f1.y);
            }
        }
        __syncthreads();
    }

    // epilogue: + qB . A[n] (rank-16 LoRA), write scores
    #pragma unroll
    for (int j = 0; j < 8; j++) {
        int n = n0 + rg + 16*j;
        const float4* ap = (const float4*)(loraA + (size_t)n*RNK);
        float4 a0 = ap[0], a1 = ap[1], a2 = ap[2], a3 = ap[3];
        #pragma unroll
        for (int i = 0; i < 8; i++) {
            int b = bgq*8 + i;
            float2 f = *(float2*)&acc[i][j];
            float s = f.x + f.y;
            const float* qb = sQB[b];
            s += qb[0]*a0.x  + qb[1]*a0.y  + qb[2]*a0.z  + qb[3]*a0.w;
            s += qb[4]*a1.x  + qb[5]*a1.y  + qb[6]*a1.z  + qb[7]*a1.w;
            s += qb[8]*a2.x  + qb[9]*a2.y  + qb[10]*a2.z + qb[11]*a2.w;
            s += qb[12]*a3.x + qb[13]*a3.y + qb[14]*a3.z + qb[15]*a3.w;
            g_scores[(size_t)b*NMEM + n] = s;
        }
    }
}

// ---------------- Kernel C: top-8 per batch (sorted desc, lax.top_k order) -------
__global__ void kC() {
    int b = blockIdx.x, t = threadIdx.x;   // 256 threads
    const float* sc = g_scores + (size_t)b*NMEM;
    float bv[TOPK]; int bi[TOPK];
    #pragma unroll
    for (int k = 0; k < TOPK; k++) { bv[k] = -FLT_MAX; bi[k] = 0x7fffffff; }

    #pragma unroll 8
    for (int i = 0; i < NMEM/(256*4); i++) {
        int e4 = t + i*256;
        float4 v = *(const float4*)(sc + (size_t)e4*4);
        float vv[4] = {v.x, v.y, v.z, v.w};
        #pragma unroll
        for (int j = 0; j < 4; j++) {
            float cv = vv[j]; int ci = e4*4 + j;
            if (gtp(cv, ci, bv[TOPK-1], bi[TOPK-1])) {
                #pragma unroll
                for (int k = 0; k < TOPK; k++) {
                    if (gtp(cv, ci, bv[k], bi[k])) {
                        float tv = bv[k]; int ti = bi[k];
                        bv[k] = cv; bi[k] = ci;
                        cv = tv; ci = ti;
                    }
                }
            }
        }
    }

    __shared__ float sv[256*TOPK];
    __shared__ int   si[256*TOPK];
    __shared__ float rv[256];
    __shared__ int   ri[256];
    __shared__ int   rl[256];
    #pragma unroll
    for (int k = 0; k < TOPK; k++) { sv[t*TOPK+k] = bv[k]; si[t*TOPK+k] = bi[k]; }
    __syncthreads();

    for (int kk = 0; kk < TOPK; kk++) {
        float mv = -FLT_MAX; int mi = 0x7fffffff; int ml = 0;
        #pragma unroll
        for (int k = 0; k < TOPK; k++) {
            float v = sv[t*TOPK+k]; int ii = si[t*TOPK+k];
            if (gtp(v, ii, mv, mi)) { mv = v; mi = ii; ml = t*TOPK+k; }
        }
        rv[t] = mv; ri[t] = mi; rl[t] = ml;
        __syncthreads();
        for (int s2 = 128; s2 > 0; s2 >>= 1) {
            if (t < s2 && gtp(rv[t+s2], ri[t+s2], rv[t], ri[t])) {
                rv[t] = rv[t+s2]; ri[t] = ri[t+s2]; rl[t] = rl[t+s2];
            }
            __syncthreads();
        }
        if (t == 0) { g_topidx[b*TOPK + kk] = ri[0]; sv[rl[0]] = -FLT_MAX; }
        __syncthreads();
    }
}

// ---------------- Kernel D1: retrieved = base[idx] + A[idx]@loraB; x = sum_k -----
__global__ void kD1(const float* __restrict__ base, const float* __restrict__ loraA,
                    const float* __restrict__ loraB, float* __restrict__ out) {
    int b = blockIdx.x, t = threadIdx.x;   // 512 threads, t == d
    __shared__ int   sIdx[TOPK];
    __shared__ float sA[TOPK][RNK];
    if (t < TOPK) sIdx[t] = g_topidx[b*TOPK + t];
    __syncthreads();
    if (t < TOPK*RNK) sA[t/RNK][t%RNK] = loraA[(size_t)sIdx[t/RNK]*RNK + (t%RNK)];
    __syncthreads();
    float lb[RNK];
    #pragma unroll
    for (int r = 0; r < RNK; r++) lb[r] = loraB[r*DIM + t];
    float x = 0.f;
    #pragma unroll
    for (int k = 0; k < TOPK; k++) {
        float v = base[(size_t)sIdx[k]*DIM + t];
        #pragma unroll
        for (int r = 0; r < RNK; r++) v += sA[k][r]*lb[r];
        out[OUT_RET + ((size_t)(b*TOPK + k))*DIM + t] = v;
        x += v;
    }
    g_xT[t*BQ + b] = x;
}

// ---------------- Kernel D2: gx = x @ w_ih^T + b_ih ------------------------------
__global__ void kD2(const float* __restrict__ w_ih, const float* __restrict__ b_ih) {
    __shared__ float sW[8][DIM];
    int t = threadIdx.x, g0 = blockIdx.x*8;   // 256 threads, 8 gate rows/block
    for (int e = t; e < 8*DIM; e += 256)
        ((float*)sW)[e] = w_ih[(size_t)g0*DIM + e];
    __syncthreads();
    int b = t & 31, g = t >> 5;
    const float* xp = g_xT + b;
    const float* wp = sW[g];
    float acc = 0.f;
    #pragma unroll 8
    for (int d = 0; d < DIM; d++) acc += xp[d*BQ] * wp[d];
    g_gx[b*3*DIM + g0 + g] = acc + b_ih[g0 + g];
}

// ---------------- Kernel D2b: GRU gates (h0=0), hidden, write_prob --------------
__global__ void kD2b(const float* __restrict__ b_hh, const float* __restrict__ wg_w,
                     const float* __restrict__ wg_b, float* __restrict__ out) {
    int b = blockIdx.x, t = threadIdx.x;   // 512 threads, t == d
    float gxr = g_gx[b*3*DIM + t];
    float gxz = g_gx[b*3*DIM + DIM + t];
    float gxn = g_gx[b*3*DIM + 2*DIM + t];
    float r = sigmoidf_(gxr + b_hh[t]);
    float z = sigmoidf_(gxz + b_hh[DIM + t]);
    float n = tanhf(gxn + r*b_hh[2*DIM + t]);
    float h = (1.f - z)*n;                 // + z*h0, h0 = 0
    out[OUT_HID + b*DIM + t] = h;
    float pr = h * wg_w[t];
    #pragma unroll
    for (int o = 16; o; o >>= 1) pr += __shfl_xor_sync(0xffffffffu, pr, o);
    __shared__ float sp[16];
    if ((t & 31) == 0) sp[t >> 5] = pr;
    __syncthreads();
    if (t == 0) {
        float s = 0.f;
        #pragma unroll
        for (int i = 0; i < 16; i++) s += sp[i];
        g_p[b] = sigmoidf_(s + wg_b[0]);
    }
}

// ---------------- Kernel E: sequential-in-batch scatter into new_mem -------------
__global__ void kE(float* __restrict__ out) {
    float* mem = out + OUT_MEM;
    int t = threadIdx.x;   // 512 threads, t == d
    for (int b = 0; b < BQ; b++) {
        float p   = g_p[b];
        float add = p * g_q[b*DIM + t];
        float om  = 1.f - p;
        #pragma unroll
        for (int k = 0; k < TOPK; k++) {
            size_t off = (size_t)g_topidx[b*TOPK + k]*DIM + t;
            mem[off] = om*mem[off] + add;
        }
        __syncthreads();  // batch order matters if indices collide across batches
    }
}

// ---------------- launch ---------------------------------------------------------
extern "C" void kernel_launch(void* const* d_in, const int* in_sizes, int n_in,
                              void* d_out, int out_size) {
    const float* query = (const float*)d_in[0];
    const float* base  = (const float*)d_in[1];
    const float* loraA = (const float*)d_in[2];
    const float* loraB = (const float*)d_in[3];
    const float* w_ih  = (const float*)d_in[4];
    // d_in[5] = gru_w_hh: unused (h0 == 0)
    const float* b_ih  = (const float*)d_in[6];
    const float* b_hh  = (const float*)d_in[7];
    const float* wg_w  = (const float*)d_in[8];
    const float* wg_b  = (const float*)d_in[9];
    float* out = (float*)d_out;

    kA  <<<BQ, 256>>>(query);
    kX  <<<BQ, 256>>>(loraB);
    kY  <<<1, 32>>>();
    kB  <<<NMEM/TN, KBT>>>(base, loraA, out);   // abs launch idx 5 -> ncu target
    kC  <<<BQ, 256>>>();
    kD1 <<<BQ, DIM>>>(base, loraA, loraB, out);
    kD2 <<<(3*DIM)/8, 256>>>(w_ih, b_ih);
    kD2b<<<BQ, DIM>>>(b_hh, wg_w, wg_b, out);
    kE  <<<1, DIM>>>(out);
}

// round 4
// speedup vs baseline: 2.8557x; 2.0247x over previous
#include <cuda_runtime.h>
#include <cstdint>
#include <cfloat>
#include <math.h>

#define BQ   32
#define SEQ  128
#define DIM  512
#define NMEM 131072
#define RNK  16
#define TOPK 8

#define OUT_RET 0
#define OUT_HID (BQ*TOPK*DIM)          /* 131072 */
#define OUT_MEM (OUT_HID + BQ*DIM)     /* 147456 */

// ---------------- scratch (static device globals; no allocations) ----------------
__device__ float g_qp[4][BQ][DIM];      // partial sums for mean-q
__device__ float g_q[BQ*DIM];
__device__ float g_qB[BQ*RNK];
__device__ float g_scores[(size_t)BQ*NMEM];
__device__ float g_cv[BQ*8*TOPK];       // slice candidates (values)
__device__ int   g_ci[BQ*8*TOPK];       // slice candidates (indices)
__device__ int   g_topidx[BQ*TOPK];
__device__ float g_xT[DIM*BQ];
__device__ float g_gx[BQ*3*DIM];
__device__ float g_p[BQ];
__device__ int   g_wcnt[BQ*TOPK];       // scatter composition
__device__ float g_wcb[BQ*TOPK];
__device__ int   g_wb[BQ*TOPK][BQ];
__device__ float g_wc[BQ*TOPK][BQ];

// packed fp32x2 FMA (Blackwell; bit-exact fp32 pairs, 2x FFMA throughput)
__device__ __forceinline__ void fma2(unsigned long long& d,
                                     unsigned long long a, unsigned long long b) {
    asm("fma.rn.f32x2 %0, %1, %2, %0;" : "+l"(d) : "l"(a), "l"(b));
}

// 16-byte cp.async global->shared
__device__ __forceinline__ void cpa16(void* dst_smem, const void* src) {
    unsigned d = (unsigned)__cvta_generic_to_shared(dst_smem);
    asm volatile("cp.async.cg.shared.global [%0], [%1], 16;" :: "r"(d), "l"(src));
}
__device__ __forceinline__ void cpa_commit() {
    asm volatile("cp.async.commit_group;" ::: "memory");
}

__device__ __forceinline__ float sigmoidf_(float x) { return 1.f/(1.f + expf(-x)); }

// tie-break compare matching lax.top_k (desc value, asc index on ties)
__device__ __forceinline__ bool gtp(float v1, int i1, float v2, int i2) {
    return (v1 > v2) || (v1 == v2 && i1 < i2);
}

// ---------------- kA: partial mean over s; kA2: merge ---------------------------
__global__ void kA(const float* __restrict__ query) {
    int b = blockIdx.x, j = blockIdx.y, t = threadIdx.x;   // 512 threads, t == d
    const float* p = query + ((size_t)b*SEQ + j*32)*DIM + t;
    float acc = 0.f;
    #pragma unroll
    for (int s = 0; s < 32; s++) acc += p[(size_t)s*DIM];
    g_qp[j][b][t] = acc;
}
__global__ void kA2() {
    int b = blockIdx.x, t = threadIdx.x;   // 512 threads
    g_q[b*DIM + t] = (g_qp[0][b][t] + g_qp[1][b][t] + g_qp[2][b][t] + g_qp[3][b][t])
                     * (1.0f/SEQ);
}

// ---------------- kX: qB = q @ loraB^T ------------------------------------------
__global__ void kX(const float* __restrict__ loraB) {
    int b = blockIdx.x, t = threadIdx.x;   // 256 threads
    int w = t >> 5, lane = t & 31;
    for (int r = w; r < RNK; r += 8) {
        float acc = 0.f;
        for (int d = lane; d < DIM; d += 32) acc += g_q[b*DIM + d] * loraB[r*DIM + d];
        #pragma unroll
        for (int o = 16; o; o >>= 1) acc += __shfl_xor_sync(0xffffffffu, acc, o);
        if (lane == 0) g_qB[b*RNK + r] = acc;
    }
}

// ---------------- kB: scores for all N + fused base -> new_mem copy --------------
#define TN   128
#define DC   32
#define NCH  (DIM/DC)
#define WPAD 36      /* 144B rows: 16B-aligned granules, conflict-free LDS */
#define KBT  64

__global__ __launch_bounds__(KBT) void kB(const float* __restrict__ base,
                                          const float* __restrict__ loraA,
                                          float* __restrict__ out) {
    __shared__ float sB[2][TN][WPAD];   // 36864 B
    __shared__ float sQ[2][BQ][WPAD];   //  9216 B
    __shared__ float sQB[BQ][RNK];      //  2048 B
    const int t  = threadIdx.x;
    const int n0 = blockIdx.x * TN;
    const int w  = t >> 5, l = t & 31;
    const int bgq = (w << 1) | (l >> 4);   // 0..3 -> 8 batches each
    const int rg  = l & 15;                // rows rg + 16*j

    for (int i = t; i < BQ*RNK; i += KBT) ((float*)sQB)[i] = g_qB[i];

    auto fill = [&](int c, int buf) {
        int d0 = c*DC;
        #pragma unroll
        for (int i = 0; i < 16; i++) {
            int g = t + i*KBT;                 // 1024 16B-granules: 128 rows x 8
            int row = g >> 3, gw = g & 7;
            cpa16(&sB[buf][row][gw*4], base + (size_t)(n0+row)*DIM + d0 + gw*4);
        }
        #pragma unroll
        for (int i = 0; i < 4; i++) {
            int g = t + i*KBT;                 // 256 granules: 32 rows x 8
            int row = g >> 3, gw = g & 7;
            cpa16(&sQ[buf][row][gw*4], g_q + row*DIM + d0 + gw*4);
        }
    };

    unsigned long long acc[8][8];
    #pragma unroll
    for (int i = 0; i < 8; i++)
        #pragma unroll
        for (int j = 0; j < 8; j++) acc[i][j] = 0ull;

    float* omem = out + OUT_MEM;

    fill(0, 0); cpa_commit();

    for (int c = 0; c < NCH; c++) {
        const int buf = c & 1;
        if (c + 1 < NCH) { fill(c + 1, buf ^ 1); cpa_commit(); }
        if (c + 1 < NCH) asm volatile("cp.async.wait_group 1;" ::: "memory");
        else             asm volatile("cp.async.wait_group 0;" ::: "memory");
        __syncthreads();

        #pragma unroll 4
        for (int dd = 0; dd < DC; dd += 2) {
            unsigned long long q2[8], r2[8];
            #pragma unroll
            for (int i = 0; i < 8; i++)
                q2[i] = *(const unsigned long long*)&sQ[buf][bgq*8 + i][dd];
            #pragma unroll
            for (int j = 0; j < 8; j++)
                r2[j] = *(const unsigned long long*)&sB[buf][rg + 16*j][dd];
            #pragma unroll
            for (int i = 0; i < 8; i++)
                #pragma unroll
                for (int j = 0; j < 8; j++)
                    fma2(acc[i][j], q2[i], r2[j]);
        }

        // fused copy: smem tile -> new_mem (no extra global reads)
        {
            int d0 = c*DC;
            #pragma unroll
            for (int i = 0; i < 16; i++) {
                int g2 = t + i*KBT;            // 1024 16B-chunks: 128 rows x 8
                int row = g2 >> 3, p = g2 & 7;
                float4 v = *(const float4*)&sB[buf][row][p*4];
                *(float4*)(omem + (size_t)(n0+row)*DIM + d0 + p*4) = v;
            }
        }
        __syncthreads();
    }

    // epilogue: + qB . A[n] (rank-16 LoRA), write scores
    #pragma unroll
    for (int j = 0; j < 8; j++) {
        int n = n0 + rg + 16*j;
        const float4* ap = (const float4*)(loraA + (size_t)n*RNK);
        float4 a0 = ap[0], a1 = ap[1], a2 = ap[2], a3 = ap[3];
        #pragma unroll
        for (int i = 0; i < 8; i++) {
            int b = bgq*8 + i;
            float2 f = *(float2*)&acc[i][j];
            float s = f.x + f.y;
            const float* qb = sQB[b];
            s += qb[0]*a0.x  + qb[1]*a0.y  + qb[2]*a0.z  + qb[3]*a0.w;
            s += qb[4]*a1.x  + qb[5]*a1.y  + qb[6]*a1.z  + qb[7]*a1.w;
            s += qb[8]*a2.x  + qb[9]*a2.y  + qb[10]*a2.z + qb[11]*a2.w;
            s += qb[12]*a3.x + qb[13]*a3.y + qb[14]*a3.z + qb[15]*a3.w;
            g_scores[(size_t)b*NMEM + n] = s;
        }
    }
}

// ---------------- kC1: per-slice top-8 (32 batches x 8 slices) -------------------
#define SLICE (NMEM/8)
__global__ void kC1() {
    int b = blockIdx.x, sl = blockIdx.y, t = threadIdx.x;   // 256 threads
    const float* sc = g_scores + (size_t)b*NMEM + (size_t)sl*SLICE;
    int ibase = sl*SLICE;
    float bv[TOPK]; int bi[TOPK];
    #pragma unroll
    for (int k = 0; k < TOPK; k++) { bv[k] = -FLT_MAX; bi[k] = 0x7fffffff; }

    #pragma unroll 4
    for (int i = 0; i < SLICE/(256*4); i++) {
        int e4 = t + i*256;
        float4 v = *(const float4*)(sc + (size_t)e4*4);
        float vv[4] = {v.x, v.y, v.z, v.w};
        #pragma unroll
        for (int j = 0; j < 4; j++) {
            float cv = vv[j]; int ci = ibase + e4*4 + j;
            if (gtp(cv, ci, bv[TOPK-1], bi[TOPK-1])) {
                #pragma unroll
                for (int k = 0; k < TOPK; k++) {
                    if (gtp(cv, ci, bv[k], bi[k])) {
                        float tv = bv[k]; int ti = bi[k];
                        bv[k] = cv; bi[k] = ci;
                        cv = tv; ci = ti;
                    }
                }
            }
        }
    }

    __shared__ float sv[256*TOPK];
    __shared__ int   si[256*TOPK];
    __shared__ float rv[256];
    __shared__ int   ri[256];
    __shared__ int   rl[256];
    #pragma unroll
    for (int k = 0; k < TOPK; k++) { sv[t*TOPK+k] = bv[k]; si[t*TOPK+k] = bi[k]; }
    __syncthreads();

    for (int kk = 0; kk < TOPK; kk++) {
        float mv = -FLT_MAX; int mi = 0x7fffffff; int ml = 0;
        #pragma unroll
        for (int k = 0; k < TOPK; k++) {
            float v = sv[t*TOPK+k]; int ii = si[t*TOPK+k];
            if (gtp(v, ii, mv, mi)) { mv = v; mi = ii; ml = t*TOPK+k; }
        }
        rv[t] = mv; ri[t] = mi; rl[t] = ml;
        __syncthreads();
        for (int s2 = 128; s2 > 0; s2 >>= 1) {
            if (t < s2 && gtp(rv[t+s2], ri[t+s2], rv[t], ri[t])) {
                rv[t] = rv[t+s2]; ri[t] = ri[t+s2]; rl[t] = rl[t+s2];
            }
            __syncthreads();
        }
        if (t == 0) {
            g_cv[(b*8 + sl)*TOPK + kk] = rv[0];
            g_ci[(b*8 + sl)*TOPK + kk] = ri[0];
            sv[rl[0]] = -FLT_MAX;
        }
        __syncthreads();
    }
}

// ---------------- kC2: merge 64 candidates -> global top-8 (sorted) --------------
__global__ void kC2() {
    int b = blockIdx.x, t = threadIdx.x;   // 64 threads
    __shared__ float sv[64];
    __shared__ int   si[64];
    sv[t] = g_cv[b*64 + t];
    si[t] = g_ci[b*64 + t];
    __syncthreads();
    if (t == 0) {
        #pragma unroll
        for (int kk = 0; kk < TOPK; kk++) {
            float mv = -FLT_MAX; int mi = 0x7fffffff; int ml = 0;
            for (int i = 0; i < 64; i++)
                if (gtp(sv[i], si[i], mv, mi)) { mv = sv[i]; mi = si[i]; ml = i; }
            g_topidx[b*TOPK + kk] = mi;
            sv[ml] = -FLT_MAX;
        }
    }
}

// ---------------- kD1: retrieved = base[idx] + A[idx]@loraB; x = sum_k -----------
__global__ void kD1(const float* __restrict__ base, const float* __restrict__ loraA,
                    const float* __restrict__ loraB, float* __restrict__ out) {
    int b = blockIdx.x, t = threadIdx.x;   // 512 threads, t == d
    __shared__ int   sIdx[TOPK];
    __shared__ float sA[TOPK][RNK];
    if (t < TOPK) sIdx[t] = g_topidx[b*TOPK + t];
    __syncthreads();
    if (t < TOPK*RNK) sA[t/RNK][t%RNK] = loraA[(size_t)sIdx[t/RNK]*RNK + (t%RNK)];
    __syncthreads();
    float lb[RNK];
    #pragma unroll
    for (int r = 0; r < RNK; r++) lb[r] = loraB[r*DIM + t];
    float x = 0.f;
    #pragma unroll
    for (int k = 0; k < TOPK; k++) {
        float v = base[(size_t)sIdx[k]*DIM + t];
        #pragma unroll
        for (int r = 0; r < RNK; r++) v += sA[k][r]*lb[r];
        out[OUT_RET + ((size_t)(b*TOPK + k))*DIM + t] = v;
        x += v;
    }
    g_xT[t*BQ + b] = x;
}

// ---------------- kD2: gx = x @ w_ih^T + b_ih ------------------------------------
__global__ void kD2(const float* __restrict__ w_ih, const float* __restrict__ b_ih) {
    __shared__ float sW[8][DIM];
    int t = threadIdx.x, g0 = blockIdx.x*8;   // 256 threads, 8 gate rows/block
    for (int e = t; e < 8*DIM; e += 256)
        ((float*)sW)[e] = w_ih[(size_t)g0*DIM + e];
    __syncthreads();
    int b = t & 31, g = t >> 5;
    const float* xp = g_xT + b;
    const float* wp = sW[g];
    float acc = 0.f;
    #pragma unroll 8
    for (int d = 0; d < DIM; d++) acc += xp[d*BQ] * wp[d];
    g_gx[b*3*DIM + g0 + g] = acc + b_ih[g0 + g];
}

// ---------------- kD2b: GRU gates (h0=0), hidden, write_prob ---------------------
__global__ void kD2b(const float* __restrict__ b_hh, const float* __restrict__ wg_w,
                     const float* __restrict__ wg_b, float* __restrict__ out) {
    int b = blockIdx.x, t = threadIdx.x;   // 512 threads, t == d
    float gxr = g_gx[b*3*DIM + t];
    float gxz = g_gx[b*3*DIM + DIM + t];
    float gxn = g_gx[b*3*DIM + 2*DIM + t];
    float r = sigmoidf_(gxr + b_hh[t]);
    float z = sigmoidf_(gxz + b_hh[DIM + t]);
    float n = tanhf(gxn + r*b_hh[2*DIM + t]);
    float h = (1.f - z)*n;                 // + z*h0, h0 = 0
    out[OUT_HID + b*DIM + t] = h;
    float pr = h * wg_w[t];
    #pragma unroll
    for (int o = 16; o; o >>= 1) pr += __shfl_xor_sync(0xffffffffu, pr, o);
    __shared__ float sp[16];
    if ((t & 31) == 0) sp[t >> 5] = pr;
    __syncthreads();
    if (t == 0) {
        float s = 0.f;
        #pragma unroll
        for (int i = 0; i < 16; i++) s += sp[i];
        g_p[b] = sigmoidf_(s + wg_b[0]);
    }
}

// ---------------- kE1: compose scatter coefficients (exact scan semantics) -------
__global__ void kE1() {
    int s = threadIdx.x;                   // 256 threads = (b,k) slots
    int bs = s >> 3;
    int idx = g_topidx[s];
    // last writer of idx in batch order?
    bool last = true;
    for (int bp = bs + 1; bp < BQ; bp++) {
        #pragma unroll
        for (int k = 0; k < TOPK; k++)
            if (g_topidx[bp*TOPK + k] == idx) last = false;
    }
    if (!last) { g_wcnt[s] = 0; return; }
    // walk all batches in order, compose coefficients
    float cb = 1.f;
    float c[BQ]; int wb[BQ]; int cnt = 0;
    for (int bp = 0; bp < BQ; bp++) {
        bool hit = false;
        #pragma unroll
        for (int k = 0; k < TOPK; k++)
            if (g_topidx[bp*TOPK + k] == idx) hit = true;
        if (hit) {
            float p = g_p[bp];
            for (int j = 0; j < cnt; j++) c[j] *= (1.f - p);
            cb *= (1.f - p);
            c[cnt] = p; wb[cnt] = bp; cnt++;
        }
    }
    g_wcnt[s] = cnt;
    g_wcb[s]  = cb;
    for (int j = 0; j < cnt; j++) { g_wb[s][j] = wb[j]; g_wc[s][j] = c[j]; }
}

// ---------------- kE2: parallel scatter write ------------------------------------
__global__ void kE2(const float* __restrict__ base, float* __restrict__ out) {
    int s = blockIdx.x, t = threadIdx.x;   // 256 blocks x 512 threads
    int cnt = g_wcnt[s];
    if (cnt == 0) return;
    int idx = g_topidx[s];
    float v = g_wcb[s] * base[(size_t)idx*DIM + t];
    for (int j = 0; j < cnt; j++)
        v += g_wc[s][j] * g_q[g_wb[s][j]*DIM + t];
    out[OUT_MEM + (size_t)idx*DIM + t] = v;
}

// ---------------- launch ---------------------------------------------------------
extern "C" void kernel_launch(void* const* d_in, const int* in_sizes, int n_in,
                              void* d_out, int out_size) {
    const float* query = (const float*)d_in[0];
    const float* base  = (const float*)d_in[1];
    const float* loraA = (const float*)d_in[2];
    const float* loraB = (const float*)d_in[3];
    const float* w_ih  = (const float*)d_in[4];
    // d_in[5] = gru_w_hh: unused (h0 == 0)
    const float* b_ih  = (const float*)d_in[6];
    const float* b_hh  = (const float*)d_in[7];
    const float* wg_w  = (const float*)d_in[8];
    const float* wg_b  = (const float*)d_in[9];
    float* out = (float*)d_out;

    kA  <<<dim3(BQ,4), DIM>>>(query);
    kA2 <<<BQ, DIM>>>();
    kX  <<<BQ, 256>>>(loraB);
    kB  <<<NMEM/TN, KBT>>>(base, loraA, out);   // abs launch idx 5 -> ncu target
    kC1 <<<dim3(BQ,8), 256>>>();
    kC2 <<<BQ, 64>>>();
    kD1 <<<BQ, DIM>>>(base, loraA, loraB, out);
    kD2 <<<(3*DIM)/8, 256>>>(w_ih, b_ih);
    kD2b<<<BQ, DIM>>>(b_hh, wg_w, wg_b, out);
    kE1 <<<1, BQ*TOPK>>>();
    kE2 <<<BQ*TOPK, DIM>>>(base, out);
}